// round 13
// baseline (speedup 1.0000x reference)
#include <cuda_runtime.h>
#include <math.h>
#include <stdint.h>

#define NC 21
#define MAXN 8732
#define MAXB 128
#define OBJ 16
#define FULLW 0xffffffffu
#define ROWS 256            // rows (priors) per stream CTA

// -------- global accumulators / scratch (statically zeroed; select resets) --
__device__ double   g_loss_l     = 0.0;
__device__ double   g_loss_c     = 0.0;
__device__ int      g_npos_total = 0;
__device__ int      g_npos_b[MAXB];                 // zero-init
__device__ unsigned g_ticket     = 0;
__device__ unsigned long long g_key[MAXB * OBJ];    // zero-init; select resets
__device__ unsigned g_lc [MAXB * MAXN];             // lc bits (0 for positives)
__device__ unsigned short g_cb[MAXB * MAXN];        // unforced cls | (bti<<8)

__device__ __forceinline__ float smooth4(float4 l, float gx, float gy,
                                         float gw, float gh) {
    float d, acc = 0.0f;
    d = l.x - gx; acc += (fabsf(d) < 1.0f) ? 0.5f*d*d : fabsf(d) - 0.5f;
    d = l.y - gy; acc += (fabsf(d) < 1.0f) ? 0.5f*d*d : fabsf(d) - 0.5f;
    d = l.z - gw; acc += (fabsf(d) < 1.0f) ? 0.5f*d*d : fabsf(d) - 0.5f;
    d = l.w - gh; acc += (fabsf(d) < 1.0f) ? 0.5f*d*d : fabsf(d) - 0.5f;
    return acc;
}

// ===== kernel A: fused match + per-prior losses (bulk-async conf stream) =====
__global__ void __launch_bounds__(ROWS) loss_kernel(
        const float* __restrict__ loc,
        const float* __restrict__ conf,
        const float* __restrict__ targets,
        const float* __restrict__ priors,
        int N) {
    const int b    = blockIdx.y;
    const int r0   = blockIdx.x * ROWS;
    const int tid  = threadIdx.x;
    const int lane = tid & 31;
    const int warp = tid >> 5;

    __shared__ alignas(16) float s_conf[ROWS * NC]; // 21504 B
    __shared__ alignas(8) unsigned long long s_mbar;
    __shared__ float4 s_tv[OBJ];
    __shared__ float  s_ta[OBJ];
    __shared__ int    s_lab[OBJ];
    __shared__ unsigned long long s_key[OBJ];
    __shared__ double s_rd[8], s_rd2[8];
    __shared__ int    s_ri[8];

    const int cnt = min(ROWS, N - r0);
    const int nbytes = cnt * NC * 4;                // multiple of 16

    unsigned mbar = (unsigned)__cvta_generic_to_shared(&s_mbar);
    if (tid == 0) {
        asm volatile("mbarrier.init.shared.b64 [%0], 1;" :: "r"(mbar) : "memory");
    }
    if (tid < OBJ) {
        const float* tr = targets + ((size_t)b * OBJ + tid) * 5;
        float4 tv = make_float4(tr[0], tr[1], tr[2], tr[3]);
        s_tv[tid]  = tv;
        s_ta[tid]  = (tv.z - tv.x) * (tv.w - tv.y);
        s_lab[tid] = (int)tr[4];
        s_key[tid] = 0ULL;
    }
    __syncthreads();                                // mbar + s_tv visible

    if (tid == 0) {
        unsigned sdst = (unsigned)__cvta_generic_to_shared(s_conf);
        const float* src = conf + ((size_t)b * N + r0) * NC;
        asm volatile(
            "mbarrier.arrive.expect_tx.shared.b64 _, [%0], %1;"
            :: "r"(mbar), "r"((unsigned)nbytes) : "memory");
        asm volatile(
            "cp.async.bulk.shared::cta.global.mbarrier::complete_tx::bytes "
            "[%0], [%1], %2, [%3];"
            :: "r"(sdst), "l"(src), "r"((unsigned)nbytes), "r"(mbar) : "memory");
    }

    // matching for this CTA's priors — overlaps with the in-flight bulk copy
    const int i  = r0 + tid;
    const int ic = min(i, N - 1);                   // clamp: duplicate keys are
                                                    // identical -> atomicMax-safe
    float4 p = ((const float4*)priors)[ic];
    float px1 = p.x - p.z * 0.5f, py1 = p.y - p.w * 0.5f;
    float px2 = p.x + p.z * 0.5f, py2 = p.y + p.w * 0.5f;
    float parea = (px2 - px1) * (py2 - py1);
    unsigned lowkey = 0xFFFFFFFFu - (unsigned)ic;

    float best = -1.0f; int bj = 0;
    #pragma unroll
    for (int j = 0; j < OBJ; j++) {
        float4 tv = s_tv[j];
        float ix = fminf(tv.z, px2) - fmaxf(tv.x, px1);
        float iy = fminf(tv.w, py2) - fmaxf(tv.y, py1);
        ix = fmaxf(ix, 0.0f); iy = fmaxf(iy, 0.0f);
        float inter = ix * iy;
        float iou = __fdividef(inter, s_ta[j] + parea - inter);
        if (iou > best) { best = iou; bj = j; }     // first max over j
        unsigned long long key =
            (((unsigned long long)__float_as_uint(iou)) << 32) | lowkey;
        if (key > s_key[j]) atomicMax(&s_key[j], key);
    }

    int cls = 0;
    if (tid < cnt) {
        cls = (best < 0.5f) ? 0 : (s_lab[bj] + 1);
        g_cb[(size_t)b * N + i] = (unsigned short)(cls | (bj << 8));
    }

    // tid0-only sleepy wait (acquire), then CTA barrier publishes the tile.
    if (tid == 0) {
        unsigned done;
        do {
            asm volatile(
                "{\n\t.reg .pred p;\n\t"
                "mbarrier.try_wait.parity.acquire.cta.shared::cta.b64 p, [%1], 0, 0x989680;\n\t"
                "selp.b32 %0, 1, 0, p;\n\t}"
                : "=r"(done) : "r"(mbar) : "memory");
        } while (!done);
    }
    __syncthreads();                                // conf visible, s_key final

    if (tid < OBJ)                                  // combine CTA keys globally
        atomicMax(&g_key[b * OBJ + tid], s_key[tid]);

    double ll = 0.0, lcp = 0.0; int np = 0;

    if (tid < cnt) {
        const size_t gi = (size_t)b * N + i;
        const float* row = s_conf + tid * NC;       // stride 21: conflict-free
        float m = row[0];
        #pragma unroll
        for (int c = 1; c < NC; c++) m = fmaxf(m, row[c]);
        float s = 0.0f;
        #pragma unroll
        for (int c = 0; c < NC; c++) s += __expf(row[c] - m);
        float lse = m + __logf(s);
        float lca = lse - row[cls];
        bool pos = (cls > 0);
        g_lc[gi] = pos ? 0u : __float_as_uint(lca); // lc >= 0: monotone bits

        if (pos) {
            lcp = (double)lca; np = 1;
            float4 tv = s_tv[bj];
            float gx = ((tv.x + tv.z) * 0.5f - p.x) / (0.1f * p.z);
            float gy = ((tv.y + tv.w) * 0.5f - p.y) / (0.1f * p.w);
            float gw = logf((tv.z - tv.x) / p.z) * 5.0f;
            float gh = logf((tv.w - tv.y) / p.w) * 5.0f;
            float4 l = ((const float4*)loc)[gi];
            ll = (double)smooth4(l, gx, gy, gw, gh);
        }
    }

    #pragma unroll
    for (int off = 16; off > 0; off >>= 1) {
        ll  += __shfl_down_sync(FULLW, ll,  off);
        lcp += __shfl_down_sync(FULLW, lcp, off);
        np  += __shfl_down_sync(FULLW, np,  off);
    }
    if (lane == 0) { s_rd[warp] = ll; s_rd2[warp] = lcp; s_ri[warp] = np; }
    __syncthreads();
    if (warp == 0 && lane < 8) {
        double a = s_rd[lane], c = s_rd2[lane]; int n = s_ri[lane];
        #pragma unroll
        for (int off = 4; off > 0; off >>= 1) {
            a += __shfl_down_sync(0xFFu, a, off);
            c += __shfl_down_sync(0xFFu, c, off);
            n += __shfl_down_sync(0xFFu, n, off);
        }
        if (lane == 0 && n) {
            atomicAdd(&g_loss_l, a);
            atomicAdd(&g_loss_c, c);
            atomicAdd(&g_npos_total, n);
            atomicAdd(&g_npos_b[b], n);
        }
    }
}

// ====== kernel B: forced-match fixup + hard-negative top-K + finalize ========
// (verbatim R9/R11 select — 24-25 us measured, regs=32)
__global__ void __launch_bounds__(1024) select_kernel(
        const float* __restrict__ loc,
        const float* __restrict__ conf,
        const float* __restrict__ targets,
        const float* __restrict__ priors,
        int N, int B, float* __restrict__ out) {
    const int b    = blockIdx.x;
    const int tid  = threadIdx.x;
    const int lane = tid & 31;
    const int warp = tid >> 5;

    __shared__ unsigned s_u[MAXN];
    __shared__ unsigned s_hist[256];
    __shared__ unsigned s_prefix, s_remK;
    __shared__ double   s_d[32];
    __shared__ unsigned s_c[32];
    __shared__ int      s_fidx[OBJ];
    __shared__ unsigned char s_win[OBJ];
    __shared__ double   s_dll, s_dlc;
    __shared__ int      s_dnp;

    {   // vectorized lc load
        const uint4* src4 = (const uint4*)(g_lc + (size_t)b * N);
        uint4* dst4 = (uint4*)s_u;
        int n4 = N >> 2;
        for (int k = tid; k < n4; k += 1024) dst4[k] = src4[k];
        for (int k = (n4 << 2) + tid; k < N; k += 1024)
            s_u[k] = g_lc[(size_t)b * N + k];
    }

    // ---- forced-match fixup preamble ----
    if (tid == 0) {
        s_dll = 0.0; s_dlc = 0.0; s_dnp = 0;
        for (int j = 0; j < OBJ; j++) {
            unsigned long long k = g_key[b * OBJ + j];
            g_key[b * OBJ + j] = 0ULL;              // reset for next replay
            s_fidx[j] = (int)(0xFFFFFFFFu - (unsigned)(k & 0xFFFFFFFFu));
        }
        for (int j = 0; j < OBJ; j++) {             // winner: largest j per idx
            bool w = true;
            for (int j2 = j + 1; j2 < OBJ; j2++)
                if (s_fidx[j2] == s_fidx[j]) { w = false; break; }
            s_win[j] = w;
        }
    }
    __syncthreads();

    if (tid < OBJ && s_win[tid]) {
        const int j = tid;
        const int pi = s_fidx[j];
        const size_t gi = (size_t)b * N + pi;
        const float* cf = conf + gi * NC;
        // recompute lse with IDENTICAL op order to loss_kernel
        float r[NC];
        #pragma unroll
        for (int c = 0; c < NC; c++) r[c] = cf[c];
        float m = r[0];
        #pragma unroll
        for (int c = 1; c < NC; c++) m = fmaxf(m, r[c]);
        float s = 0.0f;
        #pragma unroll
        for (int c = 0; c < NC; c++) s += __expf(r[c] - m);
        float lse = m + __logf(s);

        unsigned short cb = g_cb[gi];
        int cls_o = cb & 0xFF;
        int bti_o = cb >> 8;

        const float* trj = targets + ((size_t)b * OBJ + j) * 5;
        int cls_n = (int)trj[4] + 1;

        float4 p = ((const float4*)priors)[pi];
        float4 l = ((const float4*)loc)[gi];

        // new forced contribution
        float gx = ((trj[0] + trj[2]) * 0.5f - p.x) / (0.1f * p.z);
        float gy = ((trj[1] + trj[3]) * 0.5f - p.y) / (0.1f * p.w);
        float gw = logf((trj[2] - trj[0]) / p.z) * 5.0f;
        float gh = logf((trj[3] - trj[1]) / p.w) * 5.0f;
        double dll = (double)smooth4(l, gx, gy, gw, gh);
        double dlc = (double)(lse - r[cls_n]);

        if (cls_o > 0) {                            // remove old pos contribution
            const float* tro = targets + ((size_t)b * OBJ + bti_o) * 5;
            float ox = ((tro[0] + tro[2]) * 0.5f - p.x) / (0.1f * p.z);
            float oy = ((tro[1] + tro[3]) * 0.5f - p.y) / (0.1f * p.w);
            float ow = logf((tro[2] - tro[0]) / p.z) * 5.0f;
            float oh = logf((tro[3] - tro[1]) / p.w) * 5.0f;
            dll -= (double)smooth4(l, ox, oy, ow, oh);
            dlc -= (double)(lse - r[cls_o]);
        } else {
            atomicAdd(&s_dnp, 1);
        }
        s_u[pi] = 0u;                               // forced prior is positive
        atomicAdd(&s_dll, dll);
        atomicAdd(&s_dlc, dlc);
    }
    __syncthreads();

    if (tid == 0) {
        if (s_dll != 0.0) atomicAdd(&g_loss_l, s_dll);
        if (s_dlc != 0.0) atomicAdd(&g_loss_c, s_dlc);
        if (s_dnp)        atomicAdd(&g_npos_total, s_dnp);
    }

    const int K = min(3 * (g_npos_b[b] + s_dnp), N - 1);
    double negsum = 0.0;                            // valid on tid 0 afterwards

    if (K > 0) {
        if (tid == 0) { s_prefix = 0u; s_remK = (unsigned)K; }
        __syncthreads();

        #pragma unroll
        for (int pass = 0; pass < 4; pass++) {
            int shift = 24 - pass * 8;
            unsigned maskAbove = (pass == 0) ? 0u : (0xFFFFFFFFu << (shift + 8));
            if (tid < 256) s_hist[tid] = 0u;
            __syncthreads();
            unsigned prefix = s_prefix;
            // plain fire-and-forget smem atomics (R2 vs R7 evidence)
            for (int i = tid; i < N; i += 1024) {
                unsigned u = s_u[i];
                if ((u & maskAbove) == prefix)
                    atomicAdd(&s_hist[(u >> shift) & 255u], 1u);
            }
            __syncthreads();
            if (tid < 32) {          // warp-0 register suffix scan over 256 bins
                unsigned h[8]; unsigned lsum = 0;
                #pragma unroll
                for (int k = 0; k < 8; k++) { h[k] = s_hist[tid*8+k]; lsum += h[k]; }
                unsigned suf = lsum;
                #pragma unroll
                for (int off = 1; off < 32; off <<= 1) {
                    unsigned v = __shfl_down_sync(FULLW, suf, off);
                    if (tid + off < 32) suf += v;
                }
                unsigned remK = s_remK;
                unsigned acc = suf - lsum;          // count in higher bins
                #pragma unroll
                for (int k = 7; k >= 0; k--) {
                    if (acc < remK && acc + h[k] >= remK) {
                        s_prefix = prefix | ((unsigned)(tid*8+k) << shift);
                        s_remK   = remK - acc;
                    }
                    acc += h[k];
                }
            }
            __syncthreads();
        }

        unsigned tbits = s_prefix;                  // K-th largest value bits
        double lsum = 0.0; unsigned cgt = 0;
        for (int i = tid; i < N; i += 1024) {
            unsigned u = s_u[i];
            if (u > tbits) { lsum += (double)__uint_as_float(u); cgt++; }
        }
        #pragma unroll
        for (int off = 16; off > 0; off >>= 1) {
            lsum += __shfl_down_sync(FULLW, lsum, off);
            cgt  += __shfl_down_sync(FULLW, cgt,  off);
        }
        if (lane == 0) { s_d[warp] = lsum; s_c[warp] = cgt; }
        __syncthreads();
        if (warp == 0) {
            double a = s_d[lane]; unsigned c = s_c[lane];
            #pragma unroll
            for (int off = 16; off > 0; off >>= 1) {
                a += __shfl_down_sync(FULLW, a, off);
                c += __shfl_down_sync(FULLW, c, off);
            }
            if (lane == 0) {
                unsigned mm = (unsigned)K - c;      // tie slots worth t each
                negsum = a + (double)mm * (double)__uint_as_float(tbits);
            }
        }
    }

    // accumulate + last-CTA finalize & reset (for next graph replay)
    if (tid == 0) {
        if (negsum != 0.0) atomicAdd(&g_loss_c, negsum);
        __threadfence();
        unsigned t = atomicAdd(&g_ticket, 1u);
        if (t == (unsigned)B - 1u) {
            __threadfence();
            double L = atomicAdd(&g_loss_l, 0.0);
            double C = atomicAdd(&g_loss_c, 0.0);
            int    n = atomicAdd(&g_npos_total, 0);
            float nf = (float)n;
            out[0] = (float)L / nf;
            out[1] = (float)C / nf;
            g_loss_l = 0.0; g_loss_c = 0.0; g_npos_total = 0;
            for (int k = 0; k < MAXB; k++) g_npos_b[k] = 0;
            __threadfence();
            g_ticket = 0u;
        }
    }
}

// ---- profile-steering no-op (makes ncu's launch index 5 = loss_kernel) -----
__global__ void dummy_kernel() {}

// ---------------- launch ----------------
extern "C" void kernel_launch(void* const* d_in, const int* in_sizes, int n_in,
                              void* d_out, int out_size) {
    const float* loc     = (const float*)d_in[0];
    const float* conf    = (const float*)d_in[1];
    const float* targets = (const float*)d_in[2];
    const float* priors  = (const float*)d_in[3];
    int N = in_sizes[3] / 4;
    int B = in_sizes[0] / (4 * N);

    dim3 g((N + ROWS - 1) / ROWS, B);
    loss_kernel<<<g, ROWS>>>(loc, conf, targets, priors, N);
    select_kernel<<<B, 1024>>>(loc, conf, targets, priors, N, B, (float*)d_out);
    // 5-launch cycle: ncu (-s 5 -c 1) lands on loss_kernel of replay 2
    dummy_kernel<<<1, 1>>>();
    dummy_kernel<<<1, 1>>>();
    dummy_kernel<<<1, 1>>>();
}

// round 14
// speedup vs baseline: 1.1448x; 1.1448x over previous
#include <cuda_runtime.h>
#include <math.h>
#include <stdint.h>

#define NC 21
#define MAXN 8732
#define MAXB 128
#define OBJ 16
#define FULLW 0xffffffffu
#define ROWS 256            // rows (priors) per tile
#define TPC 7               // tiles per CTA

// -------- global accumulators / scratch (statically zeroed; select resets) --
__device__ double   g_loss_l     = 0.0;
__device__ double   g_loss_c     = 0.0;
__device__ int      g_npos_total = 0;
__device__ int      g_npos_b[MAXB];                 // zero-init
__device__ unsigned g_ticket     = 0;
__device__ unsigned long long g_key[MAXB * OBJ];    // zero-init; select resets
__device__ unsigned g_lc [MAXB * MAXN];             // lc bits (0 for positives)
__device__ unsigned short g_cb[MAXB * MAXN];        // unforced cls | (bti<<8)

__device__ __forceinline__ float smooth4(float4 l, float gx, float gy,
                                         float gw, float gh) {
    float d, acc = 0.0f;
    d = l.x - gx; acc += (fabsf(d) < 1.0f) ? 0.5f*d*d : fabsf(d) - 0.5f;
    d = l.y - gy; acc += (fabsf(d) < 1.0f) ? 0.5f*d*d : fabsf(d) - 0.5f;
    d = l.z - gw; acc += (fabsf(d) < 1.0f) ? 0.5f*d*d : fabsf(d) - 0.5f;
    d = l.w - gh; acc += (fabsf(d) < 1.0f) ? 0.5f*d*d : fabsf(d) - 0.5f;
    return acc;
}

// == kernel A: fused match + losses; TPC tiles/CTA, double-buffered TMA ======
__global__ void __launch_bounds__(ROWS) loss_kernel(
        const float* __restrict__ loc,
        const float* __restrict__ conf,
        const float* __restrict__ targets,
        const float* __restrict__ priors,
        int N) {
    const int b    = blockIdx.y;
    const int tid  = threadIdx.x;
    const int lane = tid & 31;
    const int warp = tid >> 5;

    const int ntiles   = (N + ROWS - 1) / ROWS;
    const int t_begin  = blockIdx.x * TPC;
    const int t_end    = min(t_begin + TPC, ntiles);
    if (t_begin >= ntiles) return;

    __shared__ alignas(16) float s_conf[2][ROWS * NC];   // 2 x 21504 B
    __shared__ alignas(8) unsigned long long s_mbar[2];
    __shared__ float4 s_tv[OBJ];
    __shared__ float  s_ta[OBJ];
    __shared__ int    s_lab[OBJ];
    __shared__ unsigned long long s_key[OBJ];
    __shared__ double s_rd[8], s_rd2[8];
    __shared__ int    s_ri[8];

    unsigned mbar0 = (unsigned)__cvta_generic_to_shared(&s_mbar[0]);
    unsigned mbar1 = (unsigned)__cvta_generic_to_shared(&s_mbar[1]);

    if (tid == 0) {
        asm volatile("mbarrier.init.shared.b64 [%0], 1;" :: "r"(mbar0) : "memory");
        asm volatile("mbarrier.init.shared.b64 [%0], 1;" :: "r"(mbar1) : "memory");
    }
    if (tid < OBJ) {
        const float* tr = targets + ((size_t)b * OBJ + tid) * 5;
        float4 tv = make_float4(tr[0], tr[1], tr[2], tr[3]);
        s_tv[tid]  = tv;
        s_ta[tid]  = (tv.z - tv.x) * (tv.w - tv.y);
        s_lab[tid] = (int)tr[4];
        s_key[tid] = 0ULL;
    }
    __syncthreads();                                // mbar + s_tv visible

    // issue helper (tid 0 only)
    auto issue = [&](int t, int bsel) {
        int r0   = t * ROWS;
        int cnt  = min(ROWS, N - r0);
        unsigned nb = (unsigned)(cnt * NC * 4);     // multiple of 16
        unsigned mb = bsel ? mbar1 : mbar0;
        unsigned sdst = (unsigned)__cvta_generic_to_shared(&s_conf[bsel][0]);
        const float* src = conf + ((size_t)b * N + r0) * NC;
        asm volatile("mbarrier.arrive.expect_tx.shared.b64 _, [%0], %1;"
                     :: "r"(mb), "r"(nb) : "memory");
        asm volatile(
            "cp.async.bulk.shared::cta.global.mbarrier::complete_tx::bytes "
            "[%0], [%1], %2, [%3];"
            :: "r"(sdst), "l"(src), "r"(nb), "r"(mb) : "memory");
    };

    if (tid == 0) {                                 // prologue: fill both bufs
        issue(t_begin, 0);
        if (t_begin + 1 < t_end) issue(t_begin + 1, 1);
    }

    unsigned ph0 = 0, ph1 = 0;                      // parity per buffer (tid0)
    double ll = 0.0, lcp = 0.0; int np = 0;

    for (int t = t_begin; t < t_end; t++) {
        const int bsel = (t - t_begin) & 1;

        if (tid == 0) {                             // sleepy wait, tid0 only
            unsigned mb = bsel ? mbar1 : mbar0;
            unsigned ph = bsel ? ph1 : ph0;
            unsigned done;
            do {
                asm volatile(
                    "{\n\t.reg .pred p;\n\t"
                    "mbarrier.try_wait.parity.acquire.cta.shared::cta.b64 p, [%1], %2, 0x989680;\n\t"
                    "selp.b32 %0, 1, 0, p;\n\t}"
                    : "=r"(done) : "r"(mb), "r"(ph) : "memory");
            } while (!done);
            if (bsel) ph1 ^= 1; else ph0 ^= 1;
        }
        __syncthreads();                            // tile visible to all

        const int r0  = t * ROWS;
        const int cnt = min(ROWS, N - r0);
        const int i   = r0 + tid;
        const int ic  = min(i, N - 1);              // clamp: dup keys identical

        // ---- match (IoU over 16 truths) ----
        float4 p = ((const float4*)priors)[ic];
        float px1 = p.x - p.z * 0.5f, py1 = p.y - p.w * 0.5f;
        float px2 = p.x + p.z * 0.5f, py2 = p.y + p.w * 0.5f;
        float parea = (px2 - px1) * (py2 - py1);
        unsigned lowkey = 0xFFFFFFFFu - (unsigned)ic;

        float best = -1.0f; int bj = 0;
        #pragma unroll
        for (int j = 0; j < OBJ; j++) {
            float4 tv = s_tv[j];
            float ix = fminf(tv.z, px2) - fmaxf(tv.x, px1);
            float iy = fminf(tv.w, py2) - fmaxf(tv.y, py1);
            ix = fmaxf(ix, 0.0f); iy = fmaxf(iy, 0.0f);
            float inter = ix * iy;
            float iou = __fdividef(inter, s_ta[j] + parea - inter);
            if (iou > best) { best = iou; bj = j; }       // first max over j
            unsigned long long key =
                (((unsigned long long)__float_as_uint(iou)) << 32) | lowkey;
            if (key > s_key[j]) atomicMax(&s_key[j], key); // monotone precheck
        }

        if (tid < cnt) {
            int cls = (best < 0.5f) ? 0 : (s_lab[bj] + 1);
            const size_t gi = (size_t)b * N + i;
            g_cb[gi] = (unsigned short)(cls | (bj << 8));

            // ---- softmax losses from the staged tile ----
            const float* row = &s_conf[bsel][0] + tid * NC;  // stride 21
            float m = row[0];
            #pragma unroll
            for (int c = 1; c < NC; c++) m = fmaxf(m, row[c]);
            float s = 0.0f;
            #pragma unroll
            for (int c = 0; c < NC; c++) s += __expf(row[c] - m);
            float lse = m + __logf(s);
            float lca = lse - row[cls];
            bool pos = (cls > 0);
            g_lc[gi] = pos ? 0u : __float_as_uint(lca);  // monotone bits

            if (pos) {
                lcp += (double)lca; np++;
                float4 tv = s_tv[bj];
                float gx = ((tv.x + tv.z) * 0.5f - p.x) / (0.1f * p.z);
                float gy = ((tv.y + tv.w) * 0.5f - p.y) / (0.1f * p.w);
                float gw = logf((tv.z - tv.x) / p.z) * 5.0f;
                float gh = logf((tv.w - tv.y) / p.w) * 5.0f;
                float4 l = ((const float4*)loc)[gi];
                ll += (double)smooth4(l, gx, gy, gw, gh);
            }
        }
        __syncthreads();                            // all done reading buffer
        if (tid == 0 && t + 2 < t_end) issue(t + 2, bsel);
    }

    if (tid < OBJ)                                  // one global combine per CTA
        atomicMax(&g_key[b * OBJ + tid], s_key[tid]);

    // single block reduction for all tiles
    #pragma unroll
    for (int off = 16; off > 0; off >>= 1) {
        ll  += __shfl_down_sync(FULLW, ll,  off);
        lcp += __shfl_down_sync(FULLW, lcp, off);
        np  += __shfl_down_sync(FULLW, np,  off);
    }
    if (lane == 0) { s_rd[warp] = ll; s_rd2[warp] = lcp; s_ri[warp] = np; }
    __syncthreads();
    if (warp == 0 && lane < 8) {
        double a = s_rd[lane], c = s_rd2[lane]; int n = s_ri[lane];
        #pragma unroll
        for (int off = 4; off > 0; off >>= 1) {
            a += __shfl_down_sync(0xFFu, a, off);
            c += __shfl_down_sync(0xFFu, c, off);
            n += __shfl_down_sync(0xFFu, n, off);
        }
        if (lane == 0 && n) {
            atomicAdd(&g_loss_l, a);
            atomicAdd(&g_loss_c, c);
            atomicAdd(&g_npos_total, n);
            atomicAdd(&g_npos_b[b], n);
        }
    }
}

// ====== kernel B: forced-match fixup + hard-negative top-K + finalize ========
// (verbatim measured 24-25 us version, regs=32)
__global__ void __launch_bounds__(1024) select_kernel(
        const float* __restrict__ loc,
        const float* __restrict__ conf,
        const float* __restrict__ targets,
        const float* __restrict__ priors,
        int N, int B, float* __restrict__ out) {
    const int b    = blockIdx.x;
    const int tid  = threadIdx.x;
    const int lane = tid & 31;
    const int warp = tid >> 5;

    __shared__ unsigned s_u[MAXN];
    __shared__ unsigned s_hist[256];
    __shared__ unsigned s_prefix, s_remK;
    __shared__ double   s_d[32];
    __shared__ unsigned s_c[32];
    __shared__ int      s_fidx[OBJ];
    __shared__ unsigned char s_win[OBJ];
    __shared__ double   s_dll, s_dlc;
    __shared__ int      s_dnp;

    {   // vectorized lc load
        const uint4* src4 = (const uint4*)(g_lc + (size_t)b * N);
        uint4* dst4 = (uint4*)s_u;
        int n4 = N >> 2;
        for (int k = tid; k < n4; k += 1024) dst4[k] = src4[k];
        for (int k = (n4 << 2) + tid; k < N; k += 1024)
            s_u[k] = g_lc[(size_t)b * N + k];
    }

    // ---- forced-match fixup preamble ----
    if (tid == 0) {
        s_dll = 0.0; s_dlc = 0.0; s_dnp = 0;
        for (int j = 0; j < OBJ; j++) {
            unsigned long long k = g_key[b * OBJ + j];
            g_key[b * OBJ + j] = 0ULL;              // reset for next replay
            s_fidx[j] = (int)(0xFFFFFFFFu - (unsigned)(k & 0xFFFFFFFFu));
        }
        for (int j = 0; j < OBJ; j++) {             // winner: largest j per idx
            bool w = true;
            for (int j2 = j + 1; j2 < OBJ; j2++)
                if (s_fidx[j2] == s_fidx[j]) { w = false; break; }
            s_win[j] = w;
        }
    }
    __syncthreads();

    if (tid < OBJ && s_win[tid]) {
        const int j = tid;
        const int pi = s_fidx[j];
        const size_t gi = (size_t)b * N + pi;
        const float* cf = conf + gi * NC;
        // recompute lse with IDENTICAL op order to loss_kernel
        float r[NC];
        #pragma unroll
        for (int c = 0; c < NC; c++) r[c] = cf[c];
        float m = r[0];
        #pragma unroll
        for (int c = 1; c < NC; c++) m = fmaxf(m, r[c]);
        float s = 0.0f;
        #pragma unroll
        for (int c = 0; c < NC; c++) s += __expf(r[c] - m);
        float lse = m + __logf(s);

        unsigned short cb = g_cb[gi];
        int cls_o = cb & 0xFF;
        int bti_o = cb >> 8;

        const float* trj = targets + ((size_t)b * OBJ + j) * 5;
        int cls_n = (int)trj[4] + 1;

        float4 p = ((const float4*)priors)[pi];
        float4 l = ((const float4*)loc)[gi];

        float gx = ((trj[0] + trj[2]) * 0.5f - p.x) / (0.1f * p.z);
        float gy = ((trj[1] + trj[3]) * 0.5f - p.y) / (0.1f * p.w);
        float gw = logf((trj[2] - trj[0]) / p.z) * 5.0f;
        float gh = logf((trj[3] - trj[1]) / p.w) * 5.0f;
        double dll = (double)smooth4(l, gx, gy, gw, gh);
        double dlc = (double)(lse - r[cls_n]);

        if (cls_o > 0) {                            // remove old pos contribution
            const float* tro = targets + ((size_t)b * OBJ + bti_o) * 5;
            float ox = ((tro[0] + tro[2]) * 0.5f - p.x) / (0.1f * p.z);
            float oy = ((tro[1] + tro[3]) * 0.5f - p.y) / (0.1f * p.w);
            float ow = logf((tro[2] - tro[0]) / p.z) * 5.0f;
            float oh = logf((tro[3] - tro[1]) / p.w) * 5.0f;
            dll -= (double)smooth4(l, ox, oy, ow, oh);
            dlc -= (double)(lse - r[cls_o]);
        } else {
            atomicAdd(&s_dnp, 1);
        }
        s_u[pi] = 0u;                               // forced prior is positive
        atomicAdd(&s_dll, dll);
        atomicAdd(&s_dlc, dlc);
    }
    __syncthreads();

    if (tid == 0) {
        if (s_dll != 0.0) atomicAdd(&g_loss_l, s_dll);
        if (s_dlc != 0.0) atomicAdd(&g_loss_c, s_dlc);
        if (s_dnp)        atomicAdd(&g_npos_total, s_dnp);
    }

    const int K = min(3 * (g_npos_b[b] + s_dnp), N - 1);
    double negsum = 0.0;                            // valid on tid 0 afterwards

    if (K > 0) {
        if (tid == 0) { s_prefix = 0u; s_remK = (unsigned)K; }
        __syncthreads();

        #pragma unroll
        for (int pass = 0; pass < 4; pass++) {
            int shift = 24 - pass * 8;
            unsigned maskAbove = (pass == 0) ? 0u : (0xFFFFFFFFu << (shift + 8));
            if (tid < 256) s_hist[tid] = 0u;
            __syncthreads();
            unsigned prefix = s_prefix;
            for (int i = tid; i < N; i += 1024) {
                unsigned u = s_u[i];
                if ((u & maskAbove) == prefix)
                    atomicAdd(&s_hist[(u >> shift) & 255u], 1u);
            }
            __syncthreads();
            if (tid < 32) {          // warp-0 register suffix scan over 256 bins
                unsigned h[8]; unsigned lsum = 0;
                #pragma unroll
                for (int k = 0; k < 8; k++) { h[k] = s_hist[tid*8+k]; lsum += h[k]; }
                unsigned suf = lsum;
                #pragma unroll
                for (int off = 1; off < 32; off <<= 1) {
                    unsigned v = __shfl_down_sync(FULLW, suf, off);
                    if (tid + off < 32) suf += v;
                }
                unsigned remK = s_remK;
                unsigned acc = suf - lsum;          // count in higher bins
                #pragma unroll
                for (int k = 7; k >= 0; k--) {
                    if (acc < remK && acc + h[k] >= remK) {
                        s_prefix = prefix | ((unsigned)(tid*8+k) << shift);
                        s_remK   = remK - acc;
                    }
                    acc += h[k];
                }
            }
            __syncthreads();
        }

        unsigned tbits = s_prefix;                  // K-th largest value bits
        double lsum = 0.0; unsigned cgt = 0;
        for (int i = tid; i < N; i += 1024) {
            unsigned u = s_u[i];
            if (u > tbits) { lsum += (double)__uint_as_float(u); cgt++; }
        }
        #pragma unroll
        for (int off = 16; off > 0; off >>= 1) {
            lsum += __shfl_down_sync(FULLW, lsum, off);
            cgt  += __shfl_down_sync(FULLW, cgt,  off);
        }
        if (lane == 0) { s_d[warp] = lsum; s_c[warp] = cgt; }
        __syncthreads();
        if (warp == 0) {
            double a = s_d[lane]; unsigned c = s_c[lane];
            #pragma unroll
            for (int off = 16; off > 0; off >>= 1) {
                a += __shfl_down_sync(FULLW, a, off);
                c += __shfl_down_sync(FULLW, c, off);
            }
            if (lane == 0) {
                unsigned mm = (unsigned)K - c;      // tie slots worth t each
                negsum = a + (double)mm * (double)__uint_as_float(tbits);
            }
        }
    }

    // accumulate + last-CTA finalize & reset (for next graph replay)
    if (tid == 0) {
        if (negsum != 0.0) atomicAdd(&g_loss_c, negsum);
        __threadfence();
        unsigned t = atomicAdd(&g_ticket, 1u);
        if (t == (unsigned)B - 1u) {
            __threadfence();
            double L = atomicAdd(&g_loss_l, 0.0);
            double C = atomicAdd(&g_loss_c, 0.0);
            int    n = atomicAdd(&g_npos_total, 0);
            float nf = (float)n;
            out[0] = (float)L / nf;
            out[1] = (float)C / nf;
            g_loss_l = 0.0; g_loss_c = 0.0; g_npos_total = 0;
            for (int k = 0; k < MAXB; k++) g_npos_b[k] = 0;
            __threadfence();
            g_ticket = 0u;
        }
    }
}

// ---------------- launch ----------------
extern "C" void kernel_launch(void* const* d_in, const int* in_sizes, int n_in,
                              void* d_out, int out_size) {
    const float* loc     = (const float*)d_in[0];
    const float* conf    = (const float*)d_in[1];
    const float* targets = (const float*)d_in[2];
    const float* priors  = (const float*)d_in[3];
    int N = in_sizes[3] / 4;
    int B = in_sizes[0] / (4 * N);

    int ntiles = (N + ROWS - 1) / ROWS;
    dim3 g((ntiles + TPC - 1) / TPC, B);
    loss_kernel<<<g, ROWS>>>(loc, conf, targets, priors, N);
    select_kernel<<<B, 1024>>>(loc, conf, targets, priors, N, B, (float*)d_out);
}